// round 13
// baseline (speedup 1.0000x reference)
#include <cuda_runtime.h>

// x: (16, 256, 128, 128) fp32 -> 2x2 block sum * 0.5, then 2x2 NN upsample.
//
// R13: R9's confirmed form (float4 lane-contiguous, .cs hints, 512-thread
// blocks) with work-per-thread doubled to 8 rows (4 row pairs): 8 front-
// batched LDG.128 then 8 STG.128. Per warp this forms a 4KB pure-read burst
// followed by a 4KB pure-write burst — longer same-direction phases to cut
// DRAM read/write bus-turnaround (the residual ~18% idle).
//
// Each thread: one float4 column slot x 8 consecutive rows.
// Row = 128 floats = 32 float4; group g covers rows [8g, 8g+7].
// 16*256*16 groups x 32 slots = 2,097,152 threads = 4096 CTAs @ 512.

__global__ void __launch_bounds__(512) wfdm_kernel(
    const float4* __restrict__ in, float4* __restrict__ out)
{
    int tid = blockIdx.x * blockDim.x + threadIdx.x;

    int col   = tid & 31;      // float4 slot within row (0..31), lane-contiguous
    int group = tid >> 5;      // group of 8 rows (4 row pairs)

    int base = group * 256 + col;   // 8 rows * 32 float4/row

    // Front-batched independent loads, all lane-stride-1: 8 x LDG.128
    float4 r0 = __ldcs(&in[base]);
    float4 r1 = __ldcs(&in[base + 32]);
    float4 r2 = __ldcs(&in[base + 64]);
    float4 r3 = __ldcs(&in[base + 96]);
    float4 r4 = __ldcs(&in[base + 128]);
    float4 r5 = __ldcs(&in[base + 160]);
    float4 r6 = __ldcs(&in[base + 192]);
    float4 r7 = __ldcs(&in[base + 224]);

    float s0 = (r0.x + r0.y + r1.x + r1.y) * 0.5f;
    float s1 = (r0.z + r0.w + r1.z + r1.w) * 0.5f;
    float s2 = (r2.x + r2.y + r3.x + r3.y) * 0.5f;
    float s3 = (r2.z + r2.w + r3.z + r3.w) * 0.5f;
    float s4 = (r4.x + r4.y + r5.x + r5.y) * 0.5f;
    float s5 = (r4.z + r4.w + r5.z + r5.w) * 0.5f;
    float s6 = (r6.x + r6.y + r7.x + r7.y) * 0.5f;
    float s7 = (r6.z + r6.w + r7.z + r7.w) * 0.5f;

    float4 o0 = make_float4(s0, s0, s1, s1);
    float4 o1 = make_float4(s2, s2, s3, s3);
    float4 o2 = make_float4(s4, s4, s5, s5);
    float4 o3 = make_float4(s6, s6, s7, s7);

    // 8 x STG.128, contiguous 4KB write burst per warp
    __stcs(&out[base],       o0);
    __stcs(&out[base + 32],  o0);
    __stcs(&out[base + 64],  o1);
    __stcs(&out[base + 96],  o1);
    __stcs(&out[base + 128], o2);
    __stcs(&out[base + 160], o2);
    __stcs(&out[base + 192], o3);
    __stcs(&out[base + 224], o3);
}

extern "C" void kernel_launch(void* const* d_in, const int* in_sizes, int n_in,
                              void* d_out, int out_size)
{
    const float4* in = (const float4*)d_in[0];
    float4* out = (float4*)d_out;

    // total threads = elements / 32 (each thread covers 32 floats)
    int total = out_size / 32;   // 16*256*128*128 / 32 = 2,097,152
    int threads = 512;
    int blocks = total / threads;  // exact: 4096
    wfdm_kernel<<<blocks, threads>>>(in, out);
}

// round 14
// speedup vs baseline: 1.0086x; 1.0086x over previous
#include <cuda_runtime.h>

// x: (16, 256, 128, 128) fp32 -> 2x2 block sum * 0.5, then 2x2 NN upsample.
//
// FINAL: confirmed optimum across 13 rounds (benched 81.70us R9, 81.86us R12).
//   - float4 lane-contiguous accesses (perfect 128B/warp-quarter coalescing)
//   - 4 front-batched LDG.128 (MLP=4) + 4 STG.128 per thread
//   - .cs evict-first hints (537 MB streams through 126 MB L2 exactly once)
//   - 512-thread blocks (geometry sweep: 256->82.0, 512->81.7, 1024->82.3)
//
// Roofline: pinned at the GB300 mixed read/write HBM3e stream ceiling
// (80-82% DRAM, ~6.4-6.5 TB/s). Falsified levers: MLP depth (2/4/8 equal),
// 256-bit accesses (neutral), persistence (regressed: store fences serialize
// the loop), work-per-thread 32B (neutral/worse), r/w burst clustering
// (neutral: controller sees an interleaved stream regardless). Compute <6%,
// issue ~8% -- memory controller efficiency is the hard limit.
//
// Each thread: one float4 column slot x two row pairs (4 consecutive rows).
// Row = 128 floats = 32 float4. 16*256*32 groups x 32 slots = 4,194,304
// threads = 8192 CTAs @ 512.

__global__ void __launch_bounds__(512) wfdm_kernel(
    const float4* __restrict__ in, float4* __restrict__ out)
{
    int tid = blockIdx.x * blockDim.x + threadIdx.x;

    int col   = tid & 31;      // float4 slot within row (0..31), lane-contiguous
    int group = tid >> 5;      // group of 4 rows (2 row pairs)

    int base = group * 128 + col;   // 4 rows * 32 float4/row

    // Front-batched independent loads, all lane-stride-1: MLP = 4
    float4 t0 = __ldcs(&in[base]);         // row 4g
    float4 b0 = __ldcs(&in[base + 32]);    // row 4g+1
    float4 t1 = __ldcs(&in[base + 64]);    // row 4g+2
    float4 b1 = __ldcs(&in[base + 96]);    // row 4g+3

    // Row pair 0
    float s0 = (t0.x + t0.y + b0.x + b0.y) * 0.5f;
    float s1 = (t0.z + t0.w + b0.z + b0.w) * 0.5f;
    // Row pair 1
    float s2 = (t1.x + t1.y + b1.x + b1.y) * 0.5f;
    float s3 = (t1.z + t1.w + b1.z + b1.w) * 0.5f;

    float4 o0 = make_float4(s0, s0, s1, s1);
    float4 o1 = make_float4(s2, s2, s3, s3);

    __stcs(&out[base],      o0);
    __stcs(&out[base + 32], o0);
    __stcs(&out[base + 64], o1);
    __stcs(&out[base + 96], o1);
}

extern "C" void kernel_launch(void* const* d_in, const int* in_sizes, int n_in,
                              void* d_out, int out_size)
{
    const float4* in = (const float4*)d_in[0];
    float4* out = (float4*)d_out;

    // total threads = elements / 16 (each thread covers 16 floats)
    int total = out_size / 16;   // 16*256*128*128 / 16 = 4,194,304
    int threads = 512;
    int blocks = total / threads;  // exact: 8192
    wfdm_kernel<<<blocks, threads>>>(in, out);
}